// round 4
// baseline (speedup 1.0000x reference)
#include <cuda_runtime.h>

// ---------------------------------------------------------------------------
// SpatialAttn2: B=16, L=32, N=256, P=16, H=4, F=12, HID=4, W=16
// out[B,W,F,N] | attn1[B,W,H,N,N] | attn2[B,W,N,N] | Wv1 | Wv2
// R4: split layer1 (grid 1024, CTA per head) / layer2 (grid 256) kernels,
//     h1 staged via __device__ global, no max-subtraction, plain FFMA+__expf.
// ---------------------------------------------------------------------------

#define N_   256
#define P_   16
#define H_   4
#define F_   12
#define HID_ 4
#define W_   16
#define L_   32
#define BW_  256

static const unsigned long long OFF_A1  = 786432ull;
static const unsigned long long OFF_A2  = 786432ull + 67108864ull;
static const unsigned long long OFF_WV1 = 786432ull + 67108864ull + 16777216ull;
static const unsigned long long OFF_WV2 = OFF_WV1 + 256ull;
static const long long TOT_FULL = 84672960ll;

__device__ unsigned int g_maskbits[N_ * 8];
__device__ float g_h1[BW_ * P_ * N_];   // h1 transposed per tile: [bw][i][n]

// ---------------------------------------------------------------------------
__global__ void pack_mask_kernel(const int* __restrict__ mask,
                                 const float* __restrict__ Wv1,
                                 const float* __restrict__ Wv2,
                                 float* __restrict__ out, int wW) {
    int t = blockIdx.x * 256 + threadIdx.x;
    int row  = t >> 3;
    int word = t & 7;
    const int* mr = mask + row * N_ + word * 32;
    unsigned int v = 0u;
#pragma unroll
    for (int b = 0; b < 32; b++) v |= (mr[b] > 0 ? (1u << b) : 0u);
    g_maskbits[t] = v;
    if (wW && blockIdx.x == 0) {
        out[OFF_WV1 + threadIdx.x] = Wv1[threadIdx.x];
        if (threadIdx.x < 192) out[OFF_WV2 + threadIdx.x] = Wv2[threadIdx.x];
    }
}

__device__ __forceinline__ float warp_sum(float v) {
#pragma unroll
    for (int o = 16; o > 0; o >>= 1) v += __shfl_xor_sync(0xffffffffu, v, o);
    return v;
}

// ---------------------------------------------------------------------------
// Layer 1: one CTA per (bw, h). 256 threads, 8 warps x 32 rows.
// ---------------------------------------------------------------------------
struct __align__(16) Smem1 {
    float xT [P_][N_];
    float Qs [N_][20];
    float VT [HID_][N_];
    unsigned int mb[N_][8];
    float Wa1h[P_][P_];
    float Wv1h[P_][HID_];
};

__global__ void __launch_bounds__(256, 2)
layer1_kernel(const float* __restrict__ inp,
              const float* __restrict__ Wa1,
              const float* __restrict__ Wv1,
              float* __restrict__ out, int wA) {
    extern __shared__ char smraw[];
    Smem1& S = *reinterpret_cast<Smem1*>(smraw);
    const int tid  = threadIdx.x;
    const int lane = tid & 31;
    const int wid  = tid >> 5;
    const int bw   = blockIdx.x >> 2;
    const int h    = blockIdx.x & 3;
    const int b    = bw >> 4;
    const int w    = bw & 15;

    // stage 0: loads
#pragma unroll
    for (int p = 0; p < P_; p++)
        S.xT[p][tid] = inp[(b * L_ + w + p) * N_ + tid];
#pragma unroll
    for (int k = 0; k < 8; k++)
        (&S.mb[0][0])[tid + 256 * k] = g_maskbits[tid + 256 * k];
    (&S.Wa1h[0][0])[tid] = Wa1[h * 256 + tid];
    if (tid < 64) (&S.Wv1h[0][0])[tid] = Wv1[h * 64 + tid];
    __syncthreads();

    // stage 1: Q = 0.25 * X @ Wa1[h] ; VT = (X @ Wv1[h])^T
    {
        float q[P_], v[HID_];
#pragma unroll
        for (int j = 0; j < P_; j++) q[j] = 0.f;
#pragma unroll
        for (int o = 0; o < HID_; o++) v[o] = 0.f;
#pragma unroll
        for (int i = 0; i < P_; i++) {
            float xi = S.xT[i][tid];
#pragma unroll
            for (int j = 0; j < P_; j++) q[j] += xi * S.Wa1h[i][j];
#pragma unroll
            for (int o = 0; o < HID_; o++) v[o] += xi * S.Wv1h[i][o];
        }
#pragma unroll
        for (int j4 = 0; j4 < 4; j4++) {
            float4 t4 = make_float4(q[j4*4+0]*0.25f, q[j4*4+1]*0.25f,
                                    q[j4*4+2]*0.25f, q[j4*4+3]*0.25f);
            *reinterpret_cast<float4*>(&S.Qs[tid][j4*4]) = t4;
        }
#pragma unroll
        for (int o = 0; o < HID_; o++) S.VT[o][tid] = v[o];
    }
    __syncthreads();

    float* a1h = out + OFF_A1
               + (unsigned long long)bw * (H_ * N_ * N_)
               + (unsigned long long)h * (N_ * N_);
    float* h1o = g_h1 + (bw * P_ + h * HID_) * N_;

#pragma unroll 1
    for (int rg = 0; rg < 8; rg++) {
        const int row0 = (wid << 5) + (rg << 2);
        // scores: 4 rows, lane owns cols {lane*4, 128+lane*4}; q streamed
        float4 s4[2][4];
#pragma unroll
        for (int c = 0; c < 2; c++)
#pragma unroll
            for (int r = 0; r < 4; r++) s4[c][r] = make_float4(0.f, 0.f, 0.f, 0.f);
#pragma unroll
        for (int kk = 0; kk < 4; kk++) {
            float4 q4[4];
#pragma unroll
            for (int r = 0; r < 4; r++)
                q4[r] = *reinterpret_cast<const float4*>(&S.Qs[row0 + r][kk * 4]);
#pragma unroll
            for (int k = 0; k < 4; k++) {
                const int i = kk * 4 + k;
                float qk[4];
                qk[0] = (k == 0) ? q4[0].x : (k == 1) ? q4[0].y : (k == 2) ? q4[0].z : q4[0].w;
                qk[1] = (k == 0) ? q4[1].x : (k == 1) ? q4[1].y : (k == 2) ? q4[1].z : q4[1].w;
                qk[2] = (k == 0) ? q4[2].x : (k == 1) ? q4[2].y : (k == 2) ? q4[2].z : q4[2].w;
                qk[3] = (k == 0) ? q4[3].x : (k == 1) ? q4[3].y : (k == 2) ? q4[3].z : q4[3].w;
#pragma unroll
                for (int c = 0; c < 2; c++) {
                    float4 xv = *reinterpret_cast<const float4*>(
                        &S.xT[i][c * 128 + (lane << 2)]);
#pragma unroll
                    for (int r = 0; r < 4; r++) {
                        s4[c][r].x += qk[r] * xv.x;
                        s4[c][r].y += qk[r] * xv.y;
                        s4[c][r].z += qk[r] * xv.z;
                        s4[c][r].w += qk[r] * xv.w;
                    }
                }
            }
        }
        // mask + exp (no max subtraction) + sum
        float e[4][8];
        float inv[4];
#pragma unroll
        for (int r = 0; r < 4; r++) {
            unsigned sh  = (lane & 7) << 2;
            unsigned mw0 = S.mb[row0 + r][(lane >> 3)];
            unsigned mw1 = S.mb[row0 + r][4 + (lane >> 3)];
            unsigned bb  = ((mw0 >> sh) & 0xFu) | (((mw1 >> sh) & 0xFu) << 4);
            float sm = 0.f;
#pragma unroll
            for (int c = 0; c < 2; c++) {
                const float* sp = &s4[c][r].x;
#pragma unroll
                for (int k = 0; k < 4; k++) {
                    float ee = ((bb >> (c * 4 + k)) & 1u) ? __expf(sp[k]) : 0.f;
                    e[r][c * 4 + k] = ee;
                    sm += ee;
                }
            }
            sm = warp_sum(sm);
            inv[r] = __frcp_rn(sm);
        }
        // normalize, write attn, aggregate
        float acc[4][HID_];
#pragma unroll
        for (int r = 0; r < 4; r++)
#pragma unroll
            for (int o = 0; o < HID_; o++) acc[r][o] = 0.f;
#pragma unroll
        for (int c = 0; c < 2; c++) {
            const int m0 = c * 128 + (lane << 2);
            float4 en[4];
#pragma unroll
            for (int r = 0; r < 4; r++) {
                en[r].x = e[r][c*4+0] * inv[r];
                en[r].y = e[r][c*4+1] * inv[r];
                en[r].z = e[r][c*4+2] * inv[r];
                en[r].w = e[r][c*4+3] * inv[r];
                if (wA)
                    *reinterpret_cast<float4*>(&a1h[(row0 + r) * N_ + m0]) = en[r];
            }
#pragma unroll
            for (int o = 0; o < HID_; o++) {
                float4 vv = *reinterpret_cast<const float4*>(&S.VT[o][m0]);
#pragma unroll
                for (int r = 0; r < 4; r++)
                    acc[r][o] += en[r].x * vv.x + en[r].y * vv.y
                               + en[r].z * vv.z + en[r].w * vv.w;
            }
        }
#pragma unroll
        for (int r = 0; r < 4; r++) {
#pragma unroll
            for (int o = 0; o < HID_; o++) acc[r][o] = warp_sum(acc[r][o]);
            if (lane == 0) {
#pragma unroll
                for (int o = 0; o < HID_; o++)
                    h1o[o * N_ + row0 + r] = acc[r][o];
            }
        }
    }
}

// ---------------------------------------------------------------------------
// Layer 2: one CTA per bw. 256 threads, 2-row blocking.
// ---------------------------------------------------------------------------
struct __align__(16) Smem2 {
    float h1T[P_][N_];
    float Qs [N_][20];
    float VT [F_][N_];
    unsigned int mb[N_][8];
    float Wa2[P_][P_];
    float Wv2[P_][F_];
};

__global__ void __launch_bounds__(256, 2)
layer2_kernel(const float* __restrict__ Wa2,
              const float* __restrict__ Wv2,
              float* __restrict__ out, int wA) {
    extern __shared__ char smraw[];
    Smem2& S = *reinterpret_cast<Smem2*>(smraw);
    const int tid  = threadIdx.x;
    const int lane = tid & 31;
    const int wid  = tid >> 5;
    const int bw   = blockIdx.x;

#pragma unroll
    for (int p = 0; p < P_; p++)
        S.h1T[p][tid] = g_h1[(bw * P_ + p) * N_ + tid];
#pragma unroll
    for (int k = 0; k < 8; k++)
        (&S.mb[0][0])[tid + 256 * k] = g_maskbits[tid + 256 * k];
    (&S.Wa2[0][0])[tid] = Wa2[tid];
    if (tid < 192) (&S.Wv2[0][0])[tid] = Wv2[tid];
    __syncthreads();

    {
        float q[P_], v[F_];
#pragma unroll
        for (int j = 0; j < P_; j++) q[j] = 0.f;
#pragma unroll
        for (int o = 0; o < F_; o++) v[o] = 0.f;
#pragma unroll
        for (int i = 0; i < P_; i++) {
            float xi = S.h1T[i][tid];
#pragma unroll
            for (int j = 0; j < P_; j++) q[j] += xi * S.Wa2[i][j];
#pragma unroll
            for (int o = 0; o < F_; o++) v[o] += xi * S.Wv2[i][o];
        }
#pragma unroll
        for (int j4 = 0; j4 < 4; j4++) {
            float4 t4 = make_float4(q[j4*4+0]*0.25f, q[j4*4+1]*0.25f,
                                    q[j4*4+2]*0.25f, q[j4*4+3]*0.25f);
            *reinterpret_cast<float4*>(&S.Qs[tid][j4*4]) = t4;
        }
#pragma unroll
        for (int o = 0; o < F_; o++) S.VT[o][tid] = v[o];
    }
    __syncthreads();

    float* a2 = out + OFF_A2 + (unsigned long long)bw * (N_ * N_);

#pragma unroll 1
    for (int rg = 0; rg < 16; rg++) {
        const int row0 = (wid << 5) + (rg << 1);
        float4 s4[2][2];
#pragma unroll
        for (int c = 0; c < 2; c++)
#pragma unroll
            for (int r = 0; r < 2; r++) s4[c][r] = make_float4(0.f, 0.f, 0.f, 0.f);
#pragma unroll
        for (int kk = 0; kk < 4; kk++) {
            float4 q4[2];
#pragma unroll
            for (int r = 0; r < 2; r++)
                q4[r] = *reinterpret_cast<const float4*>(&S.Qs[row0 + r][kk * 4]);
#pragma unroll
            for (int k = 0; k < 4; k++) {
                const int i = kk * 4 + k;
                float qk[2];
                qk[0] = (k == 0) ? q4[0].x : (k == 1) ? q4[0].y : (k == 2) ? q4[0].z : q4[0].w;
                qk[1] = (k == 0) ? q4[1].x : (k == 1) ? q4[1].y : (k == 2) ? q4[1].z : q4[1].w;
#pragma unroll
                for (int c = 0; c < 2; c++) {
                    float4 xv = *reinterpret_cast<const float4*>(
                        &S.h1T[i][c * 128 + (lane << 2)]);
#pragma unroll
                    for (int r = 0; r < 2; r++) {
                        s4[c][r].x += qk[r] * xv.x;
                        s4[c][r].y += qk[r] * xv.y;
                        s4[c][r].z += qk[r] * xv.z;
                        s4[c][r].w += qk[r] * xv.w;
                    }
                }
            }
        }
        float e[2][8];
        float inv[2];
#pragma unroll
        for (int r = 0; r < 2; r++) {
            unsigned sh  = (lane & 7) << 2;
            unsigned mw0 = S.mb[row0 + r][(lane >> 3)];
            unsigned mw1 = S.mb[row0 + r][4 + (lane >> 3)];
            unsigned bb  = ((mw0 >> sh) & 0xFu) | (((mw1 >> sh) & 0xFu) << 4);
            float sm = 0.f;
#pragma unroll
            for (int c = 0; c < 2; c++) {
                const float* sp = &s4[c][r].x;
#pragma unroll
                for (int k = 0; k < 4; k++) {
                    float ee = ((bb >> (c * 4 + k)) & 1u) ? __expf(sp[k]) : 0.f;
                    e[r][c * 4 + k] = ee;
                    sm += ee;
                }
            }
            sm = warp_sum(sm);
            inv[r] = __frcp_rn(sm);
        }
        float acc[2][F_];
#pragma unroll
        for (int r = 0; r < 2; r++)
#pragma unroll
            for (int o = 0; o < F_; o++) acc[r][o] = 0.f;
#pragma unroll
        for (int c = 0; c < 2; c++) {
            const int m0 = c * 128 + (lane << 2);
            float4 en[2];
#pragma unroll
            for (int r = 0; r < 2; r++) {
                en[r].x = e[r][c*4+0] * inv[r];
                en[r].y = e[r][c*4+1] * inv[r];
                en[r].z = e[r][c*4+2] * inv[r];
                en[r].w = e[r][c*4+3] * inv[r];
                if (wA)
                    *reinterpret_cast<float4*>(&a2[(row0 + r) * N_ + m0]) = en[r];
            }
#pragma unroll
            for (int o = 0; o < F_; o++) {
                float4 vv = *reinterpret_cast<const float4*>(&S.VT[o][m0]);
#pragma unroll
                for (int r = 0; r < 2; r++)
                    acc[r][o] += en[r].x * vv.x + en[r].y * vv.y
                               + en[r].z * vv.z + en[r].w * vv.w;
            }
        }
#pragma unroll
        for (int r = 0; r < 2; r++) {
#pragma unroll
            for (int o = 0; o < F_; o++) acc[r][o] = warp_sum(acc[r][o]);
            if (lane == 0) {
#pragma unroll
                for (int f = 0; f < F_; f++)
                    out[((unsigned long long)bw * F_ + f) * N_ + row0 + r] = acc[r][f];
            }
        }
    }
}

// ---------------------------------------------------------------------------
extern "C" void kernel_launch(void* const* d_in, const int* in_sizes, int n_in,
                              void* d_out, int out_size) {
    const float* inp  = (const float*)d_in[0];
    const int*   mask = (const int*)  d_in[1];
    const float* Wa1  = (const float*)d_in[2];
    const float* Wv1  = (const float*)d_in[3];
    const float* Wa2  = (const float*)d_in[4];
    const float* Wv2  = (const float*)d_in[5];
    float* out = (float*)d_out;

    const int wA = (out_size >= (int)(OFF_A2 + (unsigned long long)BW_ * N_ * N_)) ? 1 : 0;
    const int wW = (out_size >= (int)TOT_FULL) ? 1 : 0;

    cudaFuncSetAttribute(layer1_kernel,
                         cudaFuncAttributeMaxDynamicSharedMemorySize, (int)sizeof(Smem1));
    cudaFuncSetAttribute(layer2_kernel,
                         cudaFuncAttributeMaxDynamicSharedMemorySize, (int)sizeof(Smem2));

    pack_mask_kernel<<<8, 256>>>(mask, Wv1, Wv2, out, wW);
    layer1_kernel<<<BW_ * H_, 256, sizeof(Smem1)>>>(inp, Wa1, Wv1, out, wA);
    layer2_kernel<<<BW_, 256, sizeof(Smem2)>>>(Wa2, Wv2, out, wA);
}

// round 5
// speedup vs baseline: 1.3377x; 1.3377x over previous
#include <cuda_runtime.h>

// ---------------------------------------------------------------------------
// SpatialAttn2: B=16, L=32, N=256, P=16, H=4, F=12, HID=4, W=16
// out[B,W,F,N] | attn1[B,W,H,N,N] | attn2[B,W,N,N] | Wv1 | Wv2
// R5: fused kernel, 4-row layer1 + 2-row layer2, streamed q, exp-in-place,
//     no-max softmax, __launch_bounds__(256,2), ballot mask packing.
// ---------------------------------------------------------------------------

#define N_   256
#define P_   16
#define H_   4
#define F_   12
#define HID_ 4
#define W_   16
#define L_   32
#define BW_  256

static const unsigned long long OFF_A1  = 786432ull;
static const unsigned long long OFF_A2  = 786432ull + 67108864ull;
static const unsigned long long OFF_WV1 = 786432ull + 67108864ull + 16777216ull;
static const unsigned long long OFF_WV2 = OFF_WV1 + 256ull;
static const long long TOT_FULL = 84672960ll;

__device__ unsigned int g_maskbits[N_ * 8];

// ---------------------------------------------------------------------------
// prologue: ballot-packed mask bits (1 block per row) + weight passthrough
// ---------------------------------------------------------------------------
__global__ void pack_mask_kernel(const int* __restrict__ mask,
                                 const float* __restrict__ Wv1,
                                 const float* __restrict__ Wv2,
                                 float* __restrict__ out, int wW) {
    const int tid = threadIdx.x;
    const int row = blockIdx.x;
    int v = mask[row * N_ + tid];
    unsigned int bal = __ballot_sync(0xffffffffu, v > 0);
    if ((tid & 31) == 0) g_maskbits[row * 8 + (tid >> 5)] = bal;
    if (wW && row == 0) {
        out[OFF_WV1 + tid] = Wv1[tid];
        if (tid < 192) out[OFF_WV2 + tid] = Wv2[tid];
    }
}

// ---------------------------------------------------------------------------
struct __align__(16) Smem {
    float xT [P_][N_];
    float h1T[P_][N_];
    float Qs [N_][20];
    float VT [F_][N_];
    unsigned int mb[N_][8];
    float Wa1[H_][P_][P_];
    float Wv1[H_][P_][HID_];
    float Wa2[P_][P_];
    float Wv2[P_][F_];
};

__device__ __forceinline__ float warp_sum(float v) {
#pragma unroll
    for (int o = 16; o > 0; o >>= 1) v += __shfl_xor_sync(0xffffffffu, v, o);
    return v;
}

__global__ void __launch_bounds__(256, 2)
spatial_attn_kernel(const float* __restrict__ inp,
                    const float* __restrict__ Wa1,
                    const float* __restrict__ Wv1,
                    const float* __restrict__ Wa2,
                    const float* __restrict__ Wv2,
                    float* __restrict__ out, int wA) {
    extern __shared__ char smraw[];
    Smem& S = *reinterpret_cast<Smem*>(smraw);
    const int tid  = threadIdx.x;
    const int lane = tid & 31;
    const int wid  = tid >> 5;
    const int bw   = blockIdx.x;
    const int b    = bw >> 4;
    const int w    = bw & 15;

    // ---- stage 0: load xT, mask bits, weights ------------------------------
#pragma unroll
    for (int p = 0; p < P_; p++)
        S.xT[p][tid] = inp[(b * L_ + w + p) * N_ + tid];
#pragma unroll
    for (int k = 0; k < 8; k++)
        (&S.mb[0][0])[tid + 256 * k] = g_maskbits[tid + 256 * k];
#pragma unroll
    for (int k = 0; k < 4; k++)
        (&S.Wa1[0][0][0])[tid + 256 * k] = Wa1[tid + 256 * k];
    (&S.Wv1[0][0][0])[tid] = Wv1[tid];
    (&S.Wa2[0][0])[tid]    = Wa2[tid];
    if (tid < 192) (&S.Wv2[0][0])[tid] = Wv2[tid];
    __syncthreads();

    float* a1 = out + OFF_A1 + (unsigned long long)bw * (H_ * N_ * N_);
    float* a2 = out + OFF_A2 + (unsigned long long)bw * (N_ * N_);

    // =========================== layer 1 (4 heads) ===========================
#pragma unroll 1
    for (int h = 0; h < H_; h++) {
        // stage 1: Q = 0.25 * X @ Wa1[h] ; VT = (X @ Wv1[h])^T
        {
            float q[P_], v[HID_];
#pragma unroll
            for (int j = 0; j < P_; j++) q[j] = 0.f;
#pragma unroll
            for (int o = 0; o < HID_; o++) v[o] = 0.f;
#pragma unroll
            for (int i = 0; i < P_; i++) {
                float xi = S.xT[i][tid];
#pragma unroll
                for (int j = 0; j < P_; j++) q[j] += xi * S.Wa1[h][i][j];
#pragma unroll
                for (int o = 0; o < HID_; o++) v[o] += xi * S.Wv1[h][i][o];
            }
#pragma unroll
            for (int j4 = 0; j4 < 4; j4++) {
                float4 t4 = make_float4(q[j4*4+0]*0.25f, q[j4*4+1]*0.25f,
                                        q[j4*4+2]*0.25f, q[j4*4+3]*0.25f);
                *reinterpret_cast<float4*>(&S.Qs[tid][j4*4]) = t4;
            }
#pragma unroll
            for (int o = 0; o < HID_; o++) S.VT[o][tid] = v[o];
        }
        __syncthreads();

        float* a1h = a1 + h * N_ * N_;
        // stage 2: 4 rows per pass, lane owns cols {lane*4, 128+lane*4}
#pragma unroll 1
        for (int rg = 0; rg < 8; rg++) {
            const int row0 = (wid << 5) + (rg << 2);
            float4 s4[2][4];
#pragma unroll
            for (int c = 0; c < 2; c++)
#pragma unroll
                for (int r = 0; r < 4; r++) s4[c][r] = make_float4(0.f, 0.f, 0.f, 0.f);
            // streamed q: 4 regs per row live per kk block
#pragma unroll
            for (int kk = 0; kk < 4; kk++) {
                float4 q4[4];
#pragma unroll
                for (int r = 0; r < 4; r++)
                    q4[r] = *reinterpret_cast<const float4*>(&S.Qs[row0 + r][kk * 4]);
#pragma unroll
                for (int k = 0; k < 4; k++) {
                    const int i = kk * 4 + k;
                    float qk[4];
#pragma unroll
                    for (int r = 0; r < 4; r++)
                        qk[r] = (k == 0) ? q4[r].x : (k == 1) ? q4[r].y
                              : (k == 2) ? q4[r].z : q4[r].w;
#pragma unroll
                    for (int c = 0; c < 2; c++) {
                        float4 xv = *reinterpret_cast<const float4*>(
                            &S.xT[i][c * 128 + (lane << 2)]);
#pragma unroll
                        for (int r = 0; r < 4; r++) {
                            s4[c][r].x += qk[r] * xv.x;
                            s4[c][r].y += qk[r] * xv.y;
                            s4[c][r].z += qk[r] * xv.z;
                            s4[c][r].w += qk[r] * xv.w;
                        }
                    }
                }
            }
            // mask + exp in place + sum (no max subtraction)
            float inv[4];
#pragma unroll
            for (int r = 0; r < 4; r++) {
                unsigned sh  = (lane & 7) << 2;
                unsigned mw0 = S.mb[row0 + r][(lane >> 3)];
                unsigned mw1 = S.mb[row0 + r][4 + (lane >> 3)];
                unsigned bb  = ((mw0 >> sh) & 0xFu) | (((mw1 >> sh) & 0xFu) << 4);
                float sm = 0.f;
#pragma unroll
                for (int c = 0; c < 2; c++) {
                    float4& v = s4[c][r];
                    v.x = ((bb >> (c*4+0)) & 1u) ? __expf(v.x) : 0.f;
                    v.y = ((bb >> (c*4+1)) & 1u) ? __expf(v.y) : 0.f;
                    v.z = ((bb >> (c*4+2)) & 1u) ? __expf(v.z) : 0.f;
                    v.w = ((bb >> (c*4+3)) & 1u) ? __expf(v.w) : 0.f;
                    sm += v.x + v.y + v.z + v.w;
                }
                sm = warp_sum(sm);
                inv[r] = __frcp_rn(sm);
            }
            // normalize, write attn, aggregate
            float acc[4][HID_];
#pragma unroll
            for (int r = 0; r < 4; r++)
#pragma unroll
                for (int o = 0; o < HID_; o++) acc[r][o] = 0.f;
#pragma unroll
            for (int c = 0; c < 2; c++) {
                const int m0 = c * 128 + (lane << 2);
                float4 en[4];
#pragma unroll
                for (int r = 0; r < 4; r++) {
                    en[r].x = s4[c][r].x * inv[r];
                    en[r].y = s4[c][r].y * inv[r];
                    en[r].z = s4[c][r].z * inv[r];
                    en[r].w = s4[c][r].w * inv[r];
                    if (wA)
                        *reinterpret_cast<float4*>(&a1h[(row0 + r) * N_ + m0]) = en[r];
                }
#pragma unroll
                for (int o = 0; o < HID_; o++) {
                    float4 vv = *reinterpret_cast<const float4*>(&S.VT[o][m0]);
#pragma unroll
                    for (int r = 0; r < 4; r++)
                        acc[r][o] += en[r].x * vv.x + en[r].y * vv.y
                                   + en[r].z * vv.z + en[r].w * vv.w;
                }
            }
#pragma unroll
            for (int r = 0; r < 4; r++) {
#pragma unroll
                for (int o = 0; o < HID_; o++) acc[r][o] = warp_sum(acc[r][o]);
                if (lane == 0) {
#pragma unroll
                    for (int o = 0; o < HID_; o++)
                        S.h1T[h * HID_ + o][row0 + r] = acc[r][o];
                }
            }
        }
        __syncthreads();
    }

    // ================================ layer 2 ================================
    {
        float q[P_], v[F_];
#pragma unroll
        for (int j = 0; j < P_; j++) q[j] = 0.f;
#pragma unroll
        for (int o = 0; o < F_; o++) v[o] = 0.f;
#pragma unroll
        for (int i = 0; i < P_; i++) {
            float xi = S.h1T[i][tid];
#pragma unroll
            for (int j = 0; j < P_; j++) q[j] += xi * S.Wa2[i][j];
#pragma unroll
            for (int o = 0; o < F_; o++) v[o] += xi * S.Wv2[i][o];
        }
#pragma unroll
        for (int j4 = 0; j4 < 4; j4++) {
            float4 t4 = make_float4(q[j4*4+0]*0.25f, q[j4*4+1]*0.25f,
                                    q[j4*4+2]*0.25f, q[j4*4+3]*0.25f);
            *reinterpret_cast<float4*>(&S.Qs[tid][j4*4]) = t4;
        }
#pragma unroll
        for (int o = 0; o < F_; o++) S.VT[o][tid] = v[o];
    }
    __syncthreads();

#pragma unroll 1
    for (int rg = 0; rg < 16; rg++) {
        const int row0 = (wid << 5) + (rg << 1);
        float4 s4[2][2];
#pragma unroll
        for (int c = 0; c < 2; c++)
#pragma unroll
            for (int r = 0; r < 2; r++) s4[c][r] = make_float4(0.f, 0.f, 0.f, 0.f);
#pragma unroll
        for (int kk = 0; kk < 4; kk++) {
            float4 q4[2];
#pragma unroll
            for (int r = 0; r < 2; r++)
                q4[r] = *reinterpret_cast<const float4*>(&S.Qs[row0 + r][kk * 4]);
#pragma unroll
            for (int k = 0; k < 4; k++) {
                const int i = kk * 4 + k;
                float qk[2];
#pragma unroll
                for (int r = 0; r < 2; r++)
                    qk[r] = (k == 0) ? q4[r].x : (k == 1) ? q4[r].y
                          : (k == 2) ? q4[r].z : q4[r].w;
#pragma unroll
                for (int c = 0; c < 2; c++) {
                    float4 xv = *reinterpret_cast<const float4*>(
                        &S.h1T[i][c * 128 + (lane << 2)]);
#pragma unroll
                    for (int r = 0; r < 2; r++) {
                        s4[c][r].x += qk[r] * xv.x;
                        s4[c][r].y += qk[r] * xv.y;
                        s4[c][r].z += qk[r] * xv.z;
                        s4[c][r].w += qk[r] * xv.w;
                    }
                }
            }
        }
        float inv[2];
#pragma unroll
        for (int r = 0; r < 2; r++) {
            unsigned sh  = (lane & 7) << 2;
            unsigned mw0 = S.mb[row0 + r][(lane >> 3)];
            unsigned mw1 = S.mb[row0 + r][4 + (lane >> 3)];
            unsigned bb  = ((mw0 >> sh) & 0xFu) | (((mw1 >> sh) & 0xFu) << 4);
            float sm = 0.f;
#pragma unroll
            for (int c = 0; c < 2; c++) {
                float4& v = s4[c][r];
                v.x = ((bb >> (c*4+0)) & 1u) ? __expf(v.x) : 0.f;
                v.y = ((bb >> (c*4+1)) & 1u) ? __expf(v.y) : 0.f;
                v.z = ((bb >> (c*4+2)) & 1u) ? __expf(v.z) : 0.f;
                v.w = ((bb >> (c*4+3)) & 1u) ? __expf(v.w) : 0.f;
                sm += v.x + v.y + v.z + v.w;
            }
            sm = warp_sum(sm);
            inv[r] = __frcp_rn(sm);
        }
        float acc[2][F_];
#pragma unroll
        for (int r = 0; r < 2; r++)
#pragma unroll
            for (int o = 0; o < F_; o++) acc[r][o] = 0.f;
#pragma unroll
        for (int c = 0; c < 2; c++) {
            const int m0 = c * 128 + (lane << 2);
            float4 en[2];
#pragma unroll
            for (int r = 0; r < 2; r++) {
                en[r].x = s4[c][r].x * inv[r];
                en[r].y = s4[c][r].y * inv[r];
                en[r].z = s4[c][r].z * inv[r];
                en[r].w = s4[c][r].w * inv[r];
                if (wA)
                    *reinterpret_cast<float4*>(&a2[(row0 + r) * N_ + m0]) = en[r];
            }
#pragma unroll
            for (int o = 0; o < F_; o++) {
                float4 vv = *reinterpret_cast<const float4*>(&S.VT[o][m0]);
#pragma unroll
                for (int r = 0; r < 2; r++)
                    acc[r][o] += en[r].x * vv.x + en[r].y * vv.y
                               + en[r].z * vv.z + en[r].w * vv.w;
            }
        }
#pragma unroll
        for (int r = 0; r < 2; r++) {
#pragma unroll
            for (int o = 0; o < F_; o++) acc[r][o] = warp_sum(acc[r][o]);
            if (lane == 0) {
#pragma unroll
                for (int f = 0; f < F_; f++)
                    out[((unsigned long long)bw * F_ + f) * N_ + row0 + r] = acc[r][f];
            }
        }
    }
}

// ---------------------------------------------------------------------------
extern "C" void kernel_launch(void* const* d_in, const int* in_sizes, int n_in,
                              void* d_out, int out_size) {
    const float* inp  = (const float*)d_in[0];
    const int*   mask = (const int*)  d_in[1];
    const float* Wa1  = (const float*)d_in[2];
    const float* Wv1  = (const float*)d_in[3];
    const float* Wa2  = (const float*)d_in[4];
    const float* Wv2  = (const float*)d_in[5];
    float* out = (float*)d_out;

    const int wA = (out_size >= (int)(OFF_A2 + (unsigned long long)BW_ * N_ * N_)) ? 1 : 0;
    const int wW = (out_size >= (int)TOT_FULL) ? 1 : 0;

    cudaFuncSetAttribute(spatial_attn_kernel,
                         cudaFuncAttributeMaxDynamicSharedMemorySize,
                         (int)sizeof(Smem));

    pack_mask_kernel<<<N_, 256>>>(mask, Wv1, Wv2, out, wW);
    spatial_attn_kernel<<<BW_, 256, sizeof(Smem)>>>(inp, Wa1, Wv1, Wa2, Wv2, out, wA);
}

// round 6
// speedup vs baseline: 1.4282x; 1.0677x over previous
#include <cuda_runtime.h>

// ---------------------------------------------------------------------------
// SpatialAttn2: B=16, L=32, N=256, P=16, H=4, F=12, HID=4, W=16
// out[B,W,F,N] | attn1[B,W,H,N,N] | attn2[B,W,N,N] | Wv1 | Wv2
// R6: R5 structure + fma.rn.f32x2 packed score/norm/agg loops +
//     per-(row,lane) mask byte table. occ 2, fused kernel.
// ---------------------------------------------------------------------------

#define N_   256
#define P_   16
#define H_   4
#define F_   12
#define HID_ 4
#define W_   16
#define L_   32
#define BW_  256

static const unsigned long long OFF_A1  = 786432ull;
static const unsigned long long OFF_A2  = 786432ull + 67108864ull;
static const unsigned long long OFF_WV1 = 786432ull + 67108864ull + 16777216ull;
static const unsigned long long OFF_WV2 = OFF_WV1 + 256ull;
static const long long TOT_FULL = 84672960ll;

__device__ unsigned int g_maskbits[N_ * 8];

typedef unsigned long long u64;

__device__ __forceinline__ u64 pk2(float a, float b) {
    u64 r; asm("mov.b64 %0, {%1,%2};" : "=l"(r) : "f"(a), "f"(b)); return r;
}
__device__ __forceinline__ void upk2(u64 v, float& a, float& b) {
    asm("mov.b64 {%0,%1}, %2;" : "=f"(a), "=f"(b) : "l"(v));
}
__device__ __forceinline__ u64 fma2_(u64 a, u64 b, u64 c) {
    u64 d; asm("fma.rn.f32x2 %0, %1, %2, %3;" : "=l"(d) : "l"(a), "l"(b), "l"(c)); return d;
}
__device__ __forceinline__ u64 mul2_(u64 a, u64 b) {
    u64 d; asm("mul.rn.f32x2 %0, %1, %2;" : "=l"(d) : "l"(a), "l"(b)); return d;
}

// ---------------------------------------------------------------------------
__global__ void pack_mask_kernel(const int* __restrict__ mask,
                                 const float* __restrict__ Wv1,
                                 const float* __restrict__ Wv2,
                                 float* __restrict__ out, int wW) {
    const int tid = threadIdx.x;
    const int row = blockIdx.x;
    int v = mask[row * N_ + tid];
    unsigned int bal = __ballot_sync(0xffffffffu, v > 0);
    if ((tid & 31) == 0) g_maskbits[row * 8 + (tid >> 5)] = bal;
    if (wW && row == 0) {
        out[OFF_WV1 + tid] = Wv1[tid];
        if (tid < 192) out[OFF_WV2 + tid] = Wv2[tid];
    }
}

// ---------------------------------------------------------------------------
struct __align__(16) Smem {
    float xT [P_][N_];
    float h1T[P_][N_];
    float Qs [N_][20];
    float VT [F_][N_];
    unsigned char mbL[N_][32];   // per-(row,lane) mask byte
    float Wa1[H_][P_][P_];
    float Wv1[H_][P_][HID_];
    float Wa2[P_][P_];
    float Wv2[P_][F_];
};

__device__ __forceinline__ float warp_sum(float v) {
#pragma unroll
    for (int o = 16; o > 0; o >>= 1) v += __shfl_xor_sync(0xffffffffu, v, o);
    return v;
}

__global__ void __launch_bounds__(256, 2)
spatial_attn_kernel(const float* __restrict__ inp,
                    const float* __restrict__ Wa1,
                    const float* __restrict__ Wv1,
                    const float* __restrict__ Wa2,
                    const float* __restrict__ Wv2,
                    float* __restrict__ out, int wA) {
    extern __shared__ char smraw[];
    Smem& S = *reinterpret_cast<Smem*>(smraw);
    const int tid  = threadIdx.x;
    const int lane = tid & 31;
    const int wid  = tid >> 5;
    const int bw   = blockIdx.x;
    const int b    = bw >> 4;
    const int w    = bw & 15;

    // ---- stage 0: load xT, weights; build mask byte table ------------------
#pragma unroll
    for (int p = 0; p < P_; p++)
        S.xT[p][tid] = inp[(b * L_ + w + p) * N_ + tid];
    // mbL word idx = tid + 256*j ; word g of row r covers lanes 4g..4g+3
#pragma unroll
    for (int j = 0; j < 8; j++) {
        int idx = tid + 256 * j;
        int r = idx >> 3, g = idx & 7;
        unsigned A = g_maskbits[r * 8 + (g >> 1)];
        unsigned B = g_maskbits[r * 8 + 4 + (g >> 1)];
        int base = (g & 1) * 16;
        unsigned wd = 0;
#pragma unroll
        for (int i2 = 0; i2 < 4; i2++) {
            unsigned byte = ((A >> (base + 4 * i2)) & 0xFu)
                          | (((B >> (base + 4 * i2)) & 0xFu) << 4);
            wd |= byte << (8 * i2);
        }
        reinterpret_cast<unsigned*>(&S.mbL[0][0])[idx] = wd;
    }
#pragma unroll
    for (int k = 0; k < 4; k++)
        (&S.Wa1[0][0][0])[tid + 256 * k] = Wa1[tid + 256 * k];
    (&S.Wv1[0][0][0])[tid] = Wv1[tid];
    (&S.Wa2[0][0])[tid]    = Wa2[tid];
    if (tid < 192) (&S.Wv2[0][0])[tid] = Wv2[tid];
    __syncthreads();

    float* a1 = out + OFF_A1 + (unsigned long long)bw * (H_ * N_ * N_);
    float* a2 = out + OFF_A2 + (unsigned long long)bw * (N_ * N_);

    // =========================== layer 1 (4 heads) ===========================
#pragma unroll 1
    for (int h = 0; h < H_; h++) {
        // stage 1: Q = 0.25 * X @ Wa1[h] ; VT = (X @ Wv1[h])^T
        {
            float q[P_], v[HID_];
#pragma unroll
            for (int j = 0; j < P_; j++) q[j] = 0.f;
#pragma unroll
            for (int o = 0; o < HID_; o++) v[o] = 0.f;
#pragma unroll
            for (int i = 0; i < P_; i++) {
                float xi = S.xT[i][tid];
#pragma unroll
                for (int j = 0; j < P_; j++) q[j] += xi * S.Wa1[h][i][j];
#pragma unroll
                for (int o = 0; o < HID_; o++) v[o] += xi * S.Wv1[h][i][o];
            }
#pragma unroll
            for (int j4 = 0; j4 < 4; j4++) {
                float4 t4 = make_float4(q[j4*4+0]*0.25f, q[j4*4+1]*0.25f,
                                        q[j4*4+2]*0.25f, q[j4*4+3]*0.25f);
                *reinterpret_cast<float4*>(&S.Qs[tid][j4*4]) = t4;
            }
#pragma unroll
            for (int o = 0; o < HID_; o++) S.VT[o][tid] = v[o];
        }
        __syncthreads();

        float* a1h = a1 + h * N_ * N_;
#pragma unroll 1
        for (int rg = 0; rg < 8; rg++) {
            const int row0 = (wid << 5) + (rg << 2);
            // packed scores s2[c][r][pair]
            u64 s2[2][4][2];
#pragma unroll
            for (int c = 0; c < 2; c++)
#pragma unroll
                for (int r = 0; r < 4; r++) { s2[c][r][0] = 0ull; s2[c][r][1] = 0ull; }
#pragma unroll
            for (int kk = 0; kk < 4; kk++) {
                float4 q4[4];
#pragma unroll
                for (int r = 0; r < 4; r++)
                    q4[r] = *reinterpret_cast<const float4*>(&S.Qs[row0 + r][kk * 4]);
#pragma unroll
                for (int k = 0; k < 4; k++) {
                    const int i = kk * 4 + k;
                    u64 qq[4];
#pragma unroll
                    for (int r = 0; r < 4; r++) {
                        float qk = (k == 0) ? q4[r].x : (k == 1) ? q4[r].y
                                 : (k == 2) ? q4[r].z : q4[r].w;
                        qq[r] = pk2(qk, qk);
                    }
#pragma unroll
                    for (int c = 0; c < 2; c++) {
                        ulonglong2 xv = *reinterpret_cast<const ulonglong2*>(
                            &S.xT[i][c * 128 + (lane << 2)]);
#pragma unroll
                        for (int r = 0; r < 4; r++) {
                            s2[c][r][0] = fma2_(qq[r], xv.x, s2[c][r][0]);
                            s2[c][r][1] = fma2_(qq[r], xv.y, s2[c][r][1]);
                        }
                    }
                }
            }
            // mask + exp in place (no max subtraction) + sum
            float inv[4];
#pragma unroll
            for (int r = 0; r < 4; r++) {
                unsigned bb = S.mbL[row0 + r][lane];
                float sm = 0.f;
#pragma unroll
                for (int c = 0; c < 2; c++)
#pragma unroll
                    for (int p = 0; p < 2; p++) {
                        float a_, b_; upk2(s2[c][r][p], a_, b_);
                        int kb = c * 4 + p * 2;
                        a_ = ((bb >> kb) & 1u)       ? __expf(a_) : 0.f;
                        b_ = ((bb >> (kb + 1)) & 1u) ? __expf(b_) : 0.f;
                        sm += a_ + b_;
                        s2[c][r][p] = pk2(a_, b_);
                    }
                sm = warp_sum(sm);
                inv[r] = __frcp_rn(sm);
            }
            u64 inv2[4];
#pragma unroll
            for (int r = 0; r < 4; r++) inv2[r] = pk2(inv[r], inv[r]);
            // normalize (packed), write attn, aggregate (packed)
            u64 acc2[4][HID_];
#pragma unroll
            for (int r = 0; r < 4; r++)
#pragma unroll
                for (int o = 0; o < HID_; o++) acc2[r][o] = 0ull;
#pragma unroll
            for (int c = 0; c < 2; c++) {
                const int m0 = c * 128 + (lane << 2);
                u64 en[4][2];
#pragma unroll
                for (int r = 0; r < 4; r++) {
                    en[r][0] = mul2_(s2[c][r][0], inv2[r]);
                    en[r][1] = mul2_(s2[c][r][1], inv2[r]);
                    if (wA) {
                        ulonglong2 st; st.x = en[r][0]; st.y = en[r][1];
                        *reinterpret_cast<ulonglong2*>(&a1h[(row0 + r) * N_ + m0]) = st;
                    }
                }
#pragma unroll
                for (int o = 0; o < HID_; o++) {
                    ulonglong2 vv = *reinterpret_cast<const ulonglong2*>(&S.VT[o][m0]);
#pragma unroll
                    for (int r = 0; r < 4; r++) {
                        acc2[r][o] = fma2_(en[r][0], vv.x, acc2[r][o]);
                        acc2[r][o] = fma2_(en[r][1], vv.y, acc2[r][o]);
                    }
                }
            }
#pragma unroll
            for (int r = 0; r < 4; r++) {
                float hv[HID_];
#pragma unroll
                for (int o = 0; o < HID_; o++) {
                    float a_, b_; upk2(acc2[r][o], a_, b_);
                    hv[o] = warp_sum(a_ + b_);
                }
                if (lane == 0) {
#pragma unroll
                    for (int o = 0; o < HID_; o++)
                        S.h1T[h * HID_ + o][row0 + r] = hv[o];
                }
            }
        }
        __syncthreads();
    }

    // ================================ layer 2 ================================
    {
        float q[P_], v[F_];
#pragma unroll
        for (int j = 0; j < P_; j++) q[j] = 0.f;
#pragma unroll
        for (int o = 0; o < F_; o++) v[o] = 0.f;
#pragma unroll
        for (int i = 0; i < P_; i++) {
            float xi = S.h1T[i][tid];
#pragma unroll
            for (int j = 0; j < P_; j++) q[j] += xi * S.Wa2[i][j];
#pragma unroll
            for (int o = 0; o < F_; o++) v[o] += xi * S.Wv2[i][o];
        }
#pragma unroll
        for (int j4 = 0; j4 < 4; j4++) {
            float4 t4 = make_float4(q[j4*4+0]*0.25f, q[j4*4+1]*0.25f,
                                    q[j4*4+2]*0.25f, q[j4*4+3]*0.25f);
            *reinterpret_cast<float4*>(&S.Qs[tid][j4*4]) = t4;
        }
#pragma unroll
        for (int o = 0; o < F_; o++) S.VT[o][tid] = v[o];
    }
    __syncthreads();

#pragma unroll 1
    for (int rg = 0; rg < 16; rg++) {
        const int row0 = (wid << 5) + (rg << 1);
        u64 s2[2][2][2];
#pragma unroll
        for (int c = 0; c < 2; c++)
#pragma unroll
            for (int r = 0; r < 2; r++) { s2[c][r][0] = 0ull; s2[c][r][1] = 0ull; }
#pragma unroll
        for (int kk = 0; kk < 4; kk++) {
            float4 q4[2];
#pragma unroll
            for (int r = 0; r < 2; r++)
                q4[r] = *reinterpret_cast<const float4*>(&S.Qs[row0 + r][kk * 4]);
#pragma unroll
            for (int k = 0; k < 4; k++) {
                const int i = kk * 4 + k;
                u64 qq[2];
#pragma unroll
                for (int r = 0; r < 2; r++) {
                    float qk = (k == 0) ? q4[r].x : (k == 1) ? q4[r].y
                             : (k == 2) ? q4[r].z : q4[r].w;
                    qq[r] = pk2(qk, qk);
                }
#pragma unroll
                for (int c = 0; c < 2; c++) {
                    ulonglong2 xv = *reinterpret_cast<const ulonglong2*>(
                        &S.h1T[i][c * 128 + (lane << 2)]);
#pragma unroll
                    for (int r = 0; r < 2; r++) {
                        s2[c][r][0] = fma2_(qq[r], xv.x, s2[c][r][0]);
                        s2[c][r][1] = fma2_(qq[r], xv.y, s2[c][r][1]);
                    }
                }
            }
        }
        float inv[2];
#pragma unroll
        for (int r = 0; r < 2; r++) {
            unsigned bb = S.mbL[row0 + r][lane];
            float sm = 0.f;
#pragma unroll
            for (int c = 0; c < 2; c++)
#pragma unroll
                for (int p = 0; p < 2; p++) {
                    float a_, b_; upk2(s2[c][r][p], a_, b_);
                    int kb = c * 4 + p * 2;
                    a_ = ((bb >> kb) & 1u)       ? __expf(a_) : 0.f;
                    b_ = ((bb >> (kb + 1)) & 1u) ? __expf(b_) : 0.f;
                    sm += a_ + b_;
                    s2[c][r][p] = pk2(a_, b_);
                }
            sm = warp_sum(sm);
            inv[r] = __frcp_rn(sm);
        }
        u64 inv2[2];
#pragma unroll
        for (int r = 0; r < 2; r++) inv2[r] = pk2(inv[r], inv[r]);
        u64 acc2[2][F_];
#pragma unroll
        for (int r = 0; r < 2; r++)
#pragma unroll
            for (int o = 0; o < F_; o++) acc2[r][o] = 0ull;
#pragma unroll
        for (int c = 0; c < 2; c++) {
            const int m0 = c * 128 + (lane << 2);
            u64 en[2][2];
#pragma unroll
            for (int r = 0; r < 2; r++) {
                en[r][0] = mul2_(s2[c][r][0], inv2[r]);
                en[r][1] = mul2_(s2[c][r][1], inv2[r]);
                if (wA) {
                    ulonglong2 st; st.x = en[r][0]; st.y = en[r][1];
                    *reinterpret_cast<ulonglong2*>(&a2[(row0 + r) * N_ + m0]) = st;
                }
            }
#pragma unroll
            for (int o = 0; o < F_; o++) {
                ulonglong2 vv = *reinterpret_cast<const ulonglong2*>(&S.VT[o][m0]);
#pragma unroll
                for (int r = 0; r < 2; r++) {
                    acc2[r][o] = fma2_(en[r][0], vv.x, acc2[r][o]);
                    acc2[r][o] = fma2_(en[r][1], vv.y, acc2[r][o]);
                }
            }
        }
#pragma unroll
        for (int r = 0; r < 2; r++) {
            float hv[F_];
#pragma unroll
            for (int o = 0; o < F_; o++) {
                float a_, b_; upk2(acc2[r][o], a_, b_);
                hv[o] = warp_sum(a_ + b_);
            }
            if (lane == 0) {
#pragma unroll
                for (int f = 0; f < F_; f++)
                    out[((unsigned long long)bw * F_ + f) * N_ + row0 + r] = hv[f];
            }
        }
    }
}

// ---------------------------------------------------------------------------
extern "C" void kernel_launch(void* const* d_in, const int* in_sizes, int n_in,
                              void* d_out, int out_size) {
    const float* inp  = (const float*)d_in[0];
    const int*   mask = (const int*)  d_in[1];
    const float* Wa1  = (const float*)d_in[2];
    const float* Wv1  = (const float*)d_in[3];
    const float* Wa2  = (const float*)d_in[4];
    const float* Wv2  = (const float*)d_in[5];
    float* out = (float*)d_out;

    const int wA = (out_size >= (int)(OFF_A2 + (unsigned long long)BW_ * N_ * N_)) ? 1 : 0;
    const int wW = (out_size >= (int)TOT_FULL) ? 1 : 0;

    cudaFuncSetAttribute(spatial_attn_kernel,
                         cudaFuncAttributeMaxDynamicSharedMemorySize,
                         (int)sizeof(Smem));

    pack_mask_kernel<<<N_, 256>>>(mask, Wv1, Wv2, out, wW);
    spatial_attn_kernel<<<BW_, 256, sizeof(Smem)>>>(inp, Wa1, Wv1, Wa2, Wv2, out, wA);
}